// round 10
// baseline (speedup 1.0000x reference)
#include <cuda_runtime.h>
#include <math.h>

#define NN 50000
#define EE 800000

// -------- device scratch --------
__device__ float g_dis[NN];
__device__ int   g_cnt[NN];
__device__ int   g_ptr[NN + 1];
__device__ int   g_wp[NN];
__device__ int   g_csr[EE];
__device__ float g_T1[512 * 16];
__device__ float g_Wcat[128 * 32];
__device__ float g_xw[(size_t)NN * 32];
__device__ float g_h0[(size_t)NN * 16];
__device__ float g_bufR[(size_t)NN * 256];
__device__ float g_bufF[(size_t)NN * 256];
__device__ float g_sa[(size_t)NN * 16];
__device__ float g_da[(size_t)NN * 16];
__device__ int   g_samaxi[48];   // per-layer per-head global max of sa (encoded)

// -------- helpers --------
__device__ __forceinline__ float eluf(float v)  { return v > 0.f ? v : expm1f(v); }
__device__ __forceinline__ float lrelu(float v) { return v > 0.f ? v : 0.2f * v; }

__device__ __forceinline__ unsigned long long dup2(float x) {
    unsigned long long r;
    asm("mov.b64 %0, {%1, %1};" : "=l"(r) : "f"(x));
    return r;
}
__device__ __forceinline__ void fma2(unsigned long long& d, unsigned long long a, unsigned long long b) {
    asm("fma.rn.f32x2 %0, %1, %2, %0;" : "+l"(d) : "l"(a), "l"(b));
}
__device__ __forceinline__ void unpack2(unsigned long long v, float& lo, float& hi) {
    asm("mov.b64 {%0, %1}, %2;" : "=f"(lo), "=f"(hi) : "l"(v));
}
// monotone float->int encoding for atomicMax
__device__ __forceinline__ int fenc(float f) {
    int i = __float_as_int(f);
    return i < 0 ? (i ^ 0x7fffffff) : i;
}
__device__ __forceinline__ float fdec(int k) {
    return __int_as_float(k < 0 ? (k ^ 0x7fffffff) : k);
}

// -------- CSR build --------
__global__ void k_zero(int n) {
    int i = blockIdx.x * blockDim.x + threadIdx.x;
    if (i < n) g_cnt[i] = 0;
}

__global__ void k_count(const int* __restrict__ ei, int E) {
    int e = blockIdx.x * blockDim.x + threadIdx.x;
    if (e < E) atomicAdd(&g_cnt[ei[E + e]], 1);
}

// single-block exclusive scan, 8 elems/thread
__global__ void k_scan(int n) {
    __shared__ int wsum[32];
    __shared__ int s_carry;
    int tid = threadIdx.x, lane = tid & 31, wid = tid >> 5;
    if (tid == 0) s_carry = 0;
    __syncthreads();
    for (int base = 0; base < n; base += 8192) {
        int i0 = base + tid * 8;
        int v[8];
        if (i0 + 8 <= n) {
            int4 a = *(const int4*)&g_cnt[i0];
            int4 b = *(const int4*)&g_cnt[i0 + 4];
            v[0] = a.x; v[1] = a.y; v[2] = a.z; v[3] = a.w;
            v[4] = b.x; v[5] = b.y; v[6] = b.z; v[7] = b.w;
        } else {
            #pragma unroll
            for (int j = 0; j < 8; j++) v[j] = (i0 + j < n) ? g_cnt[i0 + j] : 0;
        }
        int s8 = 0;
        #pragma unroll
        for (int j = 0; j < 8; j++) s8 += v[j];
        int incl = s8;
        #pragma unroll
        for (int off = 1; off < 32; off <<= 1) {
            int y = __shfl_up_sync(0xffffffffu, incl, off);
            if (lane >= off) incl += y;
        }
        if (lane == 31) wsum[wid] = incl;
        __syncthreads();
        if (wid == 0) {
            int s = wsum[lane];
            #pragma unroll
            for (int off = 1; off < 32; off <<= 1) {
                int y = __shfl_up_sync(0xffffffffu, s, off);
                if (lane >= off) s += y;
            }
            wsum[lane] = s;
        }
        __syncthreads();
        int run = s_carry + (wid ? wsum[wid - 1] : 0) + incl - s8;
        #pragma unroll
        for (int j = 0; j < 8; j++) {
            int i = i0 + j;
            if (i < n) {
                g_ptr[i] = run;
                g_wp[i]  = run;
                g_dis[i] = rsqrtf((float)v[j] + 1.0f);
            }
            run += v[j];
        }
        int tot = wsum[31];
        __syncthreads();
        if (tid == 0) s_carry += tot;
        __syncthreads();
    }
    if (tid == 0) g_ptr[n] = s_carry;
}

__global__ void k_scatter(const int* __restrict__ ei, int E) {
    int e = blockIdx.x * blockDim.x + threadIdx.x;
    if (e < E) {
        int s = ei[e], d = ei[E + e];
        int p = atomicAdd(&g_wp[d], 1);
        g_csr[p] = s;
    }
}

__global__ void k_initmax() {
    if (threadIdx.x < 48) g_samaxi[threadIdx.x] = 0x80000000;
}

// -------- dual-conv collapse (reassociated): T1 = Hd @ Wr ; Wcat[:,16:] = Wd @ T1 --------
__global__ void __launch_bounds__(256) k_hdwr(const float* __restrict__ Hd,
                                              const float* __restrict__ Wr) {
    __shared__ float sB[512][16];
    int tid = threadIdx.x;
    #pragma unroll
    for (int i = 0; i < 8; i++)
        ((float4*)sB)[tid + 256 * i] = ((const float4*)Wr)[tid + 256 * i];
    __syncthreads();
    int r = blockIdx.x * 16 + (tid >> 4);
    int c = tid & 15;
    const float4* hp = (const float4*)&Hd[(size_t)r * 512];
    float acc = 0.f;
    #pragma unroll 4
    for (int k4 = 0; k4 < 128; k4++) {
        float4 h = hp[k4];
        acc += h.x * sB[k4 * 4 + 0][c] + h.y * sB[k4 * 4 + 1][c]
             + h.z * sB[k4 * 4 + 2][c] + h.w * sB[k4 * 4 + 3][c];
    }
    g_T1[r * 16 + c] = acc;
}

__global__ void __launch_bounds__(256) k_wdT1(const float* __restrict__ Wd,
                                              const float* __restrict__ Wgcn) {
    __shared__ float sB[512][16];
    int tid = threadIdx.x;
    #pragma unroll
    for (int i = 0; i < 8; i++)
        ((float4*)sB)[tid + 256 * i] = ((const float4*)g_T1)[tid + 256 * i];
    __syncthreads();
    int r = blockIdx.x * 16 + (tid >> 4);
    int c = tid & 15;
    const float4* ap = (const float4*)&Wd[(size_t)r * 512];
    float acc = 0.f;
    #pragma unroll 4
    for (int k4 = 0; k4 < 128; k4++) {
        float4 h = ap[k4];
        acc += h.x * sB[k4 * 4 + 0][c] + h.y * sB[k4 * 4 + 1][c]
             + h.z * sB[k4 * 4 + 2][c] + h.w * sB[k4 * 4 + 3][c];
    }
    g_Wcat[r * 32 + 16 + c] = acc;
    g_Wcat[r * 32 + c] = Wgcn[r * 16 + c];
}

// -------- XW: g_xw[N,32] = x[N,128] @ Wcat[128,32] --------
__global__ void __launch_bounds__(256) k_xw(const float* __restrict__ x, int n) {
    __shared__ __align__(16) float ws[128][32];
    __shared__ __align__(16) float xs[32][128];
    int tid = threadIdx.x;
    #pragma unroll
    for (int i = 0; i < 16; i++) { int f = tid + 256 * i; ws[f >> 5][f & 31] = g_Wcat[f]; }
    int r0 = blockIdx.x * 32;
    #pragma unroll
    for (int i = 0; i < 4; i++) {
        int idx = tid + 256 * i;
        int row = idx >> 5, c4 = idx & 31;
        float4 v = make_float4(0.f, 0.f, 0.f, 0.f);
        if (r0 + row < n) v = *(const float4*)&x[(size_t)(r0 + row) * 128 + c4 * 4];
        *(float4*)&xs[row][c4 * 4] = v;
    }
    __syncthreads();
    int c = tid & 31, rg = tid >> 5;
    float acc[4] = {0.f, 0.f, 0.f, 0.f};
    for (int k = 0; k < 128; k++) {
        float wv = ws[k][c];
        acc[0] += xs[rg][k] * wv;
        acc[1] += xs[rg + 8][k] * wv;
        acc[2] += xs[rg + 16][k] * wv;
        acc[3] += xs[rg + 24][k] * wv;
    }
    #pragma unroll
    for (int i = 0; i < 4; i++) {
        int row = r0 + rg + 8 * i;
        if (row < n) g_xw[(size_t)row * 32 + c] = acc[i];
    }
}

// -------- GCN aggregation + dual + bias + elu -> g_h0[N,16] --------
__global__ void k_gcn(const float* __restrict__ bgcn, int n) {
    int w = (blockIdx.x * blockDim.x + threadIdx.x) >> 5;
    if (w >= n) return;
    int lane = threadIdx.x & 31;
    int d = lane & 15;
    int beg = g_ptr[w], end = g_ptr[w + 1];
    float acc = 0.f;
    for (int e = beg + (lane >> 4); e < end; e += 2) {
        int s = g_csr[e];
        acc += g_dis[s] * g_xw[(size_t)s * 32 + d];
    }
    acc += __shfl_xor_sync(0xffffffffu, acc, 16);
    float dd = g_dis[w];
    acc *= dd;
    acc += dd * dd * g_xw[(size_t)w * 32 + d];
    float v = acc + bgcn[d] + g_xw[(size_t)w * 32 + 16 + d];
    v = eluf(v);
    if (lane < 16) g_h0[(size_t)w * 16 + d] = v;
}

// -------- GAT GEMM: row-paired f32x2, W pre-duplicated in SMEM --------
// tile: M=128, N=256. 256 threads. thread(tx,ty): rows ty*16+{0..15}, cols tx*8+{0..7}
__global__ void __launch_bounds__(256, 1) k_gatgemm(int K,
        const float* __restrict__ W,
        const float* __restrict__ asrc, const float* __restrict__ adst,
        int n, int layer) {
    __shared__ __align__(16) float hsT[16][128];             // [k][row]
    __shared__ __align__(16) unsigned long long wd[16][256]; // dup'd W: wd[k][c]=(w,w)
    __shared__ float s_as[256], s_ad[256];
    __shared__ int s_max[16];
    const float* __restrict__ in = (K == 16) ? (const float*)g_h0 : (const float*)g_bufF;
    float* __restrict__ raw = g_bufR;

    int tid = threadIdx.x;
    int tx = tid & 31, ty = tid >> 5;
    int r0 = blockIdx.x * 128;
    s_as[tid] = asrc[tid];
    s_ad[tid] = adst[tid];
    if (tid < 16) s_max[tid] = 0x80000000;

    unsigned long long acc[8][8];
    #pragma unroll
    for (int p = 0; p < 8; p++)
        #pragma unroll
        for (int j = 0; j < 8; j++) acc[p][j] = 0ull;

    for (int k0 = 0; k0 < K; k0 += 16) {
        __syncthreads();
        {   // input tile transposed: hsT[k][row]
            int row = tid >> 1, kk8 = (tid & 1) * 8;
            float4 va = make_float4(0.f, 0.f, 0.f, 0.f);
            float4 vb = va;
            if (r0 + row < n) {
                const float* ip = &in[(size_t)(r0 + row) * K + k0 + kk8];
                va = *(const float4*)ip;
                vb = *(const float4*)(ip + 4);
            }
            hsT[kk8 + 0][row] = va.x; hsT[kk8 + 1][row] = va.y;
            hsT[kk8 + 2][row] = va.z; hsT[kk8 + 3][row] = va.w;
            hsT[kk8 + 4][row] = vb.x; hsT[kk8 + 5][row] = vb.y;
            hsT[kk8 + 6][row] = vb.z; hsT[kk8 + 7][row] = vb.w;
        }
        #pragma unroll
        for (int p2 = 0; p2 < 4; p2++) {  // W tile, duplicated
            int kk = (tid >> 6) + p2 * 4;
            int c4 = (tid & 63) * 4;
            float4 wv = *(const float4*)&W[(size_t)(k0 + kk) * 256 + c4];
            wd[kk][c4 + 0] = dup2(wv.x);
            wd[kk][c4 + 1] = dup2(wv.y);
            wd[kk][c4 + 2] = dup2(wv.z);
            wd[kk][c4 + 3] = dup2(wv.w);
        }
        __syncthreads();
        #pragma unroll
        for (int k = 0; k < 16; k++) {
            const unsigned long long* hp = (const unsigned long long*)&hsT[k][ty * 16];
            const unsigned long long* wp = &wd[k][tx * 8];
            unsigned long long h[8], w[8];
            #pragma unroll
            for (int p = 0; p < 8; p++) h[p] = hp[p];
            #pragma unroll
            for (int j = 0; j < 8; j++) w[j] = wp[j];
            #pragma unroll
            for (int p = 0; p < 8; p++)
                #pragma unroll
                for (int j = 0; j < 8; j++)
                    fma2(acc[p][j], h[p], w[j]);
        }
    }

    // epilogue: store raw, fused sa/da + per-head global max
    int head = tx >> 1;
    int chb = (tx & 1) * 8;
    float lmax = -3.4e38f;
    #pragma unroll
    for (int p = 0; p < 8; p++) {
        float clo[8], chi[8];
        #pragma unroll
        for (int j = 0; j < 8; j++) unpack2(acc[p][j], clo[j], chi[j]);
        int row0 = r0 + ty * 16 + 2 * p;
        #pragma unroll
        for (int hh = 0; hh < 2; hh++) {
            const float* c = hh ? chi : clo;
            int row = row0 + hh;
            bool ok = row < n;
            if (ok) {
                *(float4*)&raw[(size_t)row * 256 + tx * 8]     = make_float4(c[0], c[1], c[2], c[3]);
                *(float4*)&raw[(size_t)row * 256 + tx * 8 + 4] = make_float4(c[4], c[5], c[6], c[7]);
            }
            float psa = 0.f, pda = 0.f;
            #pragma unroll
            for (int j = 0; j < 8; j++) {
                psa += c[j] * s_as[head * 16 + chb + j];
                pda += c[j] * s_ad[head * 16 + chb + j];
            }
            psa += __shfl_xor_sync(0xffffffffu, psa, 1);
            pda += __shfl_xor_sync(0xffffffffu, pda, 1);
            if (ok) {
                if ((tx & 1) == 0) {
                    g_sa[(size_t)row * 16 + head] = psa;
                    lmax = fmaxf(lmax, psa);
                } else {
                    g_da[(size_t)row * 16 + head] = pda;
                }
            }
        }
    }
    if ((tx & 1) == 0) atomicMax(&s_max[head], fenc(lmax));
    __syncthreads();
    if (tid < 16) atomicMax(&g_samaxi[layer * 16 + tid], s_max[tid]);
}

// -------- GAT aggregation: single pass using global sa-max bound --------
__global__ void k_gatagg(const float* __restrict__ bias, int n, int layer) {
    const float* __restrict__ raw = g_bufR;
    float* __restrict__ outF = g_bufF;
    int w = (blockIdx.x * blockDim.x + threadIdx.x) >> 5;
    if (w >= n) return;
    int lane = threadIdx.x & 31;
    int h16 = lane & 15;
    int beg = g_ptr[w], end = g_ptr[w + 1];
    float dval = g_da[(size_t)w * 16 + h16];
    float samax = fdec(g_samaxi[layer * 16 + h16]);
    float m = lrelu(samax + dval);   // >= true neighborhood max (lrelu monotone)

    float z = 0.f;
    float acc[8] = {0.f,0.f,0.f,0.f,0.f,0.f,0.f,0.f};
    {   // self loop
        float sa_self = g_sa[(size_t)w * 16 + h16];
        float eh = __expf(lrelu(sa_self + dval) - m);
        if (lane < 16) z += eh;
        float ew = __shfl_sync(0xffffffffu, eh, lane >> 1);
        const float4* hp = (const float4*)&raw[(size_t)w * 256 + lane * 8];
        float4 v0 = hp[0], v1 = hp[1];
        acc[0] += ew * v0.x; acc[1] += ew * v0.y; acc[2] += ew * v0.z; acc[3] += ew * v0.w;
        acc[4] += ew * v1.x; acc[5] += ew * v1.y; acc[6] += ew * v1.z; acc[7] += ew * v1.w;
    }
    #pragma unroll 2
    for (int e = beg; e < end; e++) {
        int s = g_csr[e];
        float eh = __expf(lrelu(g_sa[(size_t)s * 16 + h16] + dval) - m);
        if (lane < 16) z += eh;
        float ew = __shfl_sync(0xffffffffu, eh, lane >> 1);
        const float4* hp = (const float4*)&raw[(size_t)s * 256 + lane * 8];
        float4 v0 = hp[0], v1 = hp[1];
        acc[0] += ew * v0.x; acc[1] += ew * v0.y; acc[2] += ew * v0.z; acc[3] += ew * v0.w;
        acc[4] += ew * v1.x; acc[5] += ew * v1.y; acc[6] += ew * v1.z; acc[7] += ew * v1.w;
    }
    float zh = __shfl_sync(0xffffffffu, z, lane >> 1) + 1e-16f;
    float inv = 1.0f / zh;
    const float* bp = &bias[lane * 8];
    float4 o0, o1;
    o0.x = eluf(acc[0] * inv + bp[0]); o0.y = eluf(acc[1] * inv + bp[1]);
    o0.z = eluf(acc[2] * inv + bp[2]); o0.w = eluf(acc[3] * inv + bp[3]);
    o1.x = eluf(acc[4] * inv + bp[4]); o1.y = eluf(acc[5] * inv + bp[5]);
    o1.z = eluf(acc[6] * inv + bp[6]); o1.w = eluf(acc[7] * inv + bp[7]);
    *(float4*)&outF[(size_t)w * 256 + lane * 8]     = o0;
    *(float4*)&outF[(size_t)w * 256 + lane * 8 + 4] = o1;
}

// -------- final: concat(h[user], h[item]) @ Wdnn[512,2] -> log_softmax --------
__global__ void k_final(const float* __restrict__ Wdnn, const int* __restrict__ ui,
                        const int* __restrict__ ii, float* __restrict__ out, int Pn) {
    int p = (blockIdx.x * blockDim.x + threadIdx.x) >> 5;
    if (p >= Pn) return;
    int lane = threadIdx.x & 31;
    int u = ui[p], it = ii[p];
    float a0 = 0.f, a1 = 0.f;
    for (int i = lane; i < 512; i += 32) {
        float f = (i < 256) ? g_bufF[(size_t)u * 256 + i] : g_bufF[(size_t)it * 256 + (i - 256)];
        a0 += f * Wdnn[2 * i];
        a1 += f * Wdnn[2 * i + 1];
    }
    #pragma unroll
    for (int o = 16; o; o >>= 1) {
        a0 += __shfl_xor_sync(0xffffffffu, a0, o);
        a1 += __shfl_xor_sync(0xffffffffu, a1, o);
    }
    if (lane == 0) {
        float m = fmaxf(a0, a1);
        float l = logf(expf(a0 - m) + expf(a1 - m));
        out[2 * p]     = a0 - m - l;
        out[2 * p + 1] = a1 - m - l;
    }
}

extern "C" void kernel_launch(void* const* d_in, const int* in_sizes, int n_in,
                              void* d_out, int out_size) {
    const float* x    = (const float*)d_in[0];
    const int*   ei   = (const int*)d_in[1];
    const float* Hd   = (const float*)d_in[2];
    const int*   ui   = (const int*)d_in[3];
    const int*   ii   = (const int*)d_in[4];
    const float* Wgcn = (const float*)d_in[5];
    const float* bgcn = (const float*)d_in[6];
    const float* W1   = (const float*)d_in[7];
    const float* a1s  = (const float*)d_in[8];
    const float* a1d  = (const float*)d_in[9];
    const float* b1   = (const float*)d_in[10];
    const float* W2   = (const float*)d_in[11];
    const float* a2s  = (const float*)d_in[12];
    const float* a2d  = (const float*)d_in[13];
    const float* b2   = (const float*)d_in[14];
    const float* W3   = (const float*)d_in[15];
    const float* a3s  = (const float*)d_in[16];
    const float* a3d  = (const float*)d_in[17];
    const float* b3   = (const float*)d_in[18];
    const float* Wd   = (const float*)d_in[19];
    const float* Wr   = (const float*)d_in[20];
    const float* Wdnn = (const float*)d_in[21];
    float* out = (float*)d_out;

    int N = in_sizes[0] / 128;
    int E = in_sizes[1] / 2;
    int P = in_sizes[3];

    // CSR build + degrees
    k_zero<<<(N + 255) / 256, 256>>>(N);
    k_count<<<(E + 255) / 256, 256>>>(ei, E);
    k_scan<<<1, 1024>>>(N);
    k_scatter<<<(E + 255) / 256, 256>>>(ei, E);
    k_initmax<<<1, 64>>>();

    // dual conv collapse (reassociated): T1 = Hd@Wr ; Wcat = [Wgcn | Wd@T1]
    k_hdwr<<<32, 256>>>(Hd, Wr);
    k_wdT1<<<8, 256>>>(Wd, Wgcn);

    // xw = x @ Wcat
    k_xw<<<(N + 31) / 32, 256>>>(x, N);

    // GCN stage -> h0
    k_gcn<<<(N + 7) / 8, 256>>>(bgcn, N);

    int gB = (N + 127) / 128;
    int gA = (N + 7) / 8;

    k_gatgemm<<<gB, 256>>>(16,  W1, a1s, a1d, N, 0);
    k_gatagg<<<gA, 256>>>(b1, N, 0);
    k_gatgemm<<<gB, 256>>>(256, W2, a2s, a2d, N, 1);
    k_gatagg<<<gA, 256>>>(b2, N, 1);
    k_gatgemm<<<gB, 256>>>(256, W3, a3s, a3d, N, 2);
    k_gatagg<<<gA, 256>>>(b3, N, 2);

    k_final<<<(P + 7) / 8, 256>>>(Wdnn, ui, ii, out, P);
}

// round 11
// speedup vs baseline: 1.0036x; 1.0036x over previous
#include <cuda_runtime.h>
#include <math.h>

#define NN 50000
#define EE 800000

// -------- device scratch --------
__device__ float g_dis[NN];
__device__ int   g_cnt[NN];
__device__ int   g_ptr[NN + 1];
__device__ int   g_wp[NN];
__device__ int   g_csr[EE];
__device__ float g_T1[512 * 16];
__device__ float g_Wcat[128 * 32];
__device__ float g_xw[(size_t)NN * 32];
__device__ float g_h0[(size_t)NN * 16];
__device__ float g_bufR[(size_t)NN * 256];
__device__ float g_bufF[(size_t)NN * 256];
__device__ float g_sa[(size_t)NN * 16];
__device__ float g_da[(size_t)NN * 16];
__device__ int   g_samaxi[48];   // per-layer per-head global max of sa (encoded)

// -------- helpers --------
__device__ __forceinline__ float eluf(float v)  { return v > 0.f ? v : expm1f(v); }
__device__ __forceinline__ float lrelu(float v) { return v > 0.f ? v : 0.2f * v; }

__device__ __forceinline__ unsigned long long dup2(float x) {
    unsigned long long r;
    asm("mov.b64 %0, {%1, %1};" : "=l"(r) : "f"(x));
    return r;
}
__device__ __forceinline__ void fma2(unsigned long long& d, unsigned long long a, unsigned long long b) {
    asm("fma.rn.f32x2 %0, %1, %2, %0;" : "+l"(d) : "l"(a), "l"(b));
}
__device__ __forceinline__ void unpack2(unsigned long long v, float& lo, float& hi) {
    asm("mov.b64 {%0, %1}, %2;" : "=f"(lo), "=f"(hi) : "l"(v));
}
// monotone float->int encoding for atomicMax
__device__ __forceinline__ int fenc(float f) {
    int i = __float_as_int(f);
    return i < 0 ? (i ^ 0x7fffffff) : i;
}
__device__ __forceinline__ float fdec(int k) {
    return __int_as_float(k < 0 ? (k ^ 0x7fffffff) : k);
}

// -------- CSR build --------
__global__ void k_zero(int n) {
    int i = blockIdx.x * blockDim.x + threadIdx.x;
    if (i < n) g_cnt[i] = 0;
}

__global__ void k_count(const int* __restrict__ ei, int E) {
    int e = blockIdx.x * blockDim.x + threadIdx.x;
    if (e < E) atomicAdd(&g_cnt[ei[E + e]], 1);
}

// single-block exclusive scan, 8 elems/thread
__global__ void k_scan(int n) {
    __shared__ int wsum[32];
    __shared__ int s_carry;
    int tid = threadIdx.x, lane = tid & 31, wid = tid >> 5;
    if (tid == 0) s_carry = 0;
    __syncthreads();
    for (int base = 0; base < n; base += 8192) {
        int i0 = base + tid * 8;
        int v[8];
        if (i0 + 8 <= n) {
            int4 a = *(const int4*)&g_cnt[i0];
            int4 b = *(const int4*)&g_cnt[i0 + 4];
            v[0] = a.x; v[1] = a.y; v[2] = a.z; v[3] = a.w;
            v[4] = b.x; v[5] = b.y; v[6] = b.z; v[7] = b.w;
        } else {
            #pragma unroll
            for (int j = 0; j < 8; j++) v[j] = (i0 + j < n) ? g_cnt[i0 + j] : 0;
        }
        int s8 = 0;
        #pragma unroll
        for (int j = 0; j < 8; j++) s8 += v[j];
        int incl = s8;
        #pragma unroll
        for (int off = 1; off < 32; off <<= 1) {
            int y = __shfl_up_sync(0xffffffffu, incl, off);
            if (lane >= off) incl += y;
        }
        if (lane == 31) wsum[wid] = incl;
        __syncthreads();
        if (wid == 0) {
            int s = wsum[lane];
            #pragma unroll
            for (int off = 1; off < 32; off <<= 1) {
                int y = __shfl_up_sync(0xffffffffu, s, off);
                if (lane >= off) s += y;
            }
            wsum[lane] = s;
        }
        __syncthreads();
        int run = s_carry + (wid ? wsum[wid - 1] : 0) + incl - s8;
        #pragma unroll
        for (int j = 0; j < 8; j++) {
            int i = i0 + j;
            if (i < n) {
                g_ptr[i] = run;
                g_wp[i]  = run;
                g_dis[i] = rsqrtf((float)v[j] + 1.0f);
            }
            run += v[j];
        }
        int tot = wsum[31];
        __syncthreads();
        if (tid == 0) s_carry += tot;
        __syncthreads();
    }
    if (tid == 0) g_ptr[n] = s_carry;
}

__global__ void k_scatter(const int* __restrict__ ei, int E) {
    int e = blockIdx.x * blockDim.x + threadIdx.x;
    if (e < E) {
        int s = ei[e], d = ei[E + e];
        int p = atomicAdd(&g_wp[d], 1);
        g_csr[p] = s;
    }
}

__global__ void k_initmax() {
    if (threadIdx.x < 48) g_samaxi[threadIdx.x] = 0x80000000;
}

// -------- dual-conv collapse (reassociated): T1 = Hd @ Wr ; Wcat[:,16:] = Wd @ T1 --------
__global__ void __launch_bounds__(256) k_hdwr(const float* __restrict__ Hd,
                                              const float* __restrict__ Wr) {
    __shared__ float sB[512][16];
    int tid = threadIdx.x;
    #pragma unroll
    for (int i = 0; i < 8; i++)
        ((float4*)sB)[tid + 256 * i] = ((const float4*)Wr)[tid + 256 * i];
    __syncthreads();
    int r = blockIdx.x * 16 + (tid >> 4);
    int c = tid & 15;
    const float4* hp = (const float4*)&Hd[(size_t)r * 512];
    float acc = 0.f;
    #pragma unroll 4
    for (int k4 = 0; k4 < 128; k4++) {
        float4 h = hp[k4];
        acc += h.x * sB[k4 * 4 + 0][c] + h.y * sB[k4 * 4 + 1][c]
             + h.z * sB[k4 * 4 + 2][c] + h.w * sB[k4 * 4 + 3][c];
    }
    g_T1[r * 16 + c] = acc;
}

__global__ void __launch_bounds__(256) k_wdT1(const float* __restrict__ Wd,
                                              const float* __restrict__ Wgcn) {
    __shared__ float sB[512][16];
    int tid = threadIdx.x;
    #pragma unroll
    for (int i = 0; i < 8; i++)
        ((float4*)sB)[tid + 256 * i] = ((const float4*)g_T1)[tid + 256 * i];
    __syncthreads();
    int r = blockIdx.x * 16 + (tid >> 4);
    int c = tid & 15;
    const float4* ap = (const float4*)&Wd[(size_t)r * 512];
    float acc = 0.f;
    #pragma unroll 4
    for (int k4 = 0; k4 < 128; k4++) {
        float4 h = ap[k4];
        acc += h.x * sB[k4 * 4 + 0][c] + h.y * sB[k4 * 4 + 1][c]
             + h.z * sB[k4 * 4 + 2][c] + h.w * sB[k4 * 4 + 3][c];
    }
    g_Wcat[r * 32 + 16 + c] = acc;
    g_Wcat[r * 32 + c] = Wgcn[r * 16 + c];
}

// -------- XW: g_xw[N,32] = x[N,128] @ Wcat[128,32] --------
__global__ void __launch_bounds__(256) k_xw(const float* __restrict__ x, int n) {
    __shared__ __align__(16) float ws[128][32];
    __shared__ __align__(16) float xs[32][128];
    int tid = threadIdx.x;
    #pragma unroll
    for (int i = 0; i < 16; i++) { int f = tid + 256 * i; ws[f >> 5][f & 31] = g_Wcat[f]; }
    int r0 = blockIdx.x * 32;
    #pragma unroll
    for (int i = 0; i < 4; i++) {
        int idx = tid + 256 * i;
        int row = idx >> 5, c4 = idx & 31;
        float4 v = make_float4(0.f, 0.f, 0.f, 0.f);
        if (r0 + row < n) v = *(const float4*)&x[(size_t)(r0 + row) * 128 + c4 * 4];
        *(float4*)&xs[row][c4 * 4] = v;
    }
    __syncthreads();
    int c = tid & 31, rg = tid >> 5;
    float acc[4] = {0.f, 0.f, 0.f, 0.f};
    for (int k = 0; k < 128; k++) {
        float wv = ws[k][c];
        acc[0] += xs[rg][k] * wv;
        acc[1] += xs[rg + 8][k] * wv;
        acc[2] += xs[rg + 16][k] * wv;
        acc[3] += xs[rg + 24][k] * wv;
    }
    #pragma unroll
    for (int i = 0; i < 4; i++) {
        int row = r0 + rg + 8 * i;
        if (row < n) g_xw[(size_t)row * 32 + c] = acc[i];
    }
}

// -------- GCN aggregation + dual + bias + elu -> g_h0[N,16] --------
__global__ void k_gcn(const float* __restrict__ bgcn, int n) {
    int w = (blockIdx.x * blockDim.x + threadIdx.x) >> 5;
    if (w >= n) return;
    int lane = threadIdx.x & 31;
    int d = lane & 15;
    int beg = g_ptr[w], end = g_ptr[w + 1];
    float acc = 0.f;
    for (int e = beg + (lane >> 4); e < end; e += 2) {
        int s = g_csr[e];
        acc += g_dis[s] * g_xw[(size_t)s * 32 + d];
    }
    acc += __shfl_xor_sync(0xffffffffu, acc, 16);
    float dd = g_dis[w];
    acc *= dd;
    acc += dd * dd * g_xw[(size_t)w * 32 + d];
    float v = acc + bgcn[d] + g_xw[(size_t)w * 32 + 16 + d];
    v = eluf(v);
    if (lane < 16) g_h0[(size_t)w * 16 + d] = v;
}

// -------- GAT GEMM: row-paired f32x2, W pre-duplicated in SMEM --------
// tile: M=128, N=256. 256 threads. thread(tx,ty): rows ty*16+{0..15}, cols tx*8+{0..7}
__global__ void __launch_bounds__(256, 1) k_gatgemm(int K,
        const float* __restrict__ W,
        const float* __restrict__ asrc, const float* __restrict__ adst,
        int n, int layer) {
    __shared__ __align__(16) float hsT[16][128];             // [k][row]
    __shared__ __align__(16) unsigned long long wd[16][256]; // dup'd W: wd[k][c]=(w,w)
    __shared__ float s_as[256], s_ad[256];
    __shared__ int s_max[16];
    const float* __restrict__ in = (K == 16) ? (const float*)g_h0 : (const float*)g_bufF;
    float* __restrict__ raw = g_bufR;

    int tid = threadIdx.x;
    int tx = tid & 31, ty = tid >> 5;
    int r0 = blockIdx.x * 128;
    s_as[tid] = asrc[tid];
    s_ad[tid] = adst[tid];
    if (tid < 16) s_max[tid] = 0x80000000;

    unsigned long long acc[8][8];
    #pragma unroll
    for (int p = 0; p < 8; p++)
        #pragma unroll
        for (int j = 0; j < 8; j++) acc[p][j] = 0ull;

    for (int k0 = 0; k0 < K; k0 += 16) {
        __syncthreads();
        {   // input tile transposed: hsT[k][row]
            int row = tid >> 1, kk8 = (tid & 1) * 8;
            float4 va = make_float4(0.f, 0.f, 0.f, 0.f);
            float4 vb = va;
            if (r0 + row < n) {
                const float* ip = &in[(size_t)(r0 + row) * K + k0 + kk8];
                va = *(const float4*)ip;
                vb = *(const float4*)(ip + 4);
            }
            hsT[kk8 + 0][row] = va.x; hsT[kk8 + 1][row] = va.y;
            hsT[kk8 + 2][row] = va.z; hsT[kk8 + 3][row] = va.w;
            hsT[kk8 + 4][row] = vb.x; hsT[kk8 + 5][row] = vb.y;
            hsT[kk8 + 6][row] = vb.z; hsT[kk8 + 7][row] = vb.w;
        }
        #pragma unroll
        for (int p2 = 0; p2 < 4; p2++) {  // W tile, duplicated
            int kk = (tid >> 6) + p2 * 4;
            int c4 = (tid & 63) * 4;
            float4 wv = *(const float4*)&W[(size_t)(k0 + kk) * 256 + c4];
            wd[kk][c4 + 0] = dup2(wv.x);
            wd[kk][c4 + 1] = dup2(wv.y);
            wd[kk][c4 + 2] = dup2(wv.z);
            wd[kk][c4 + 3] = dup2(wv.w);
        }
        __syncthreads();
        #pragma unroll
        for (int k = 0; k < 16; k++) {
            const unsigned long long* hp = (const unsigned long long*)&hsT[k][ty * 16];
            const unsigned long long* wp = &wd[k][tx * 8];
            unsigned long long h[8], w[8];
            #pragma unroll
            for (int p = 0; p < 8; p++) h[p] = hp[p];
            #pragma unroll
            for (int j = 0; j < 8; j++) w[j] = wp[j];
            #pragma unroll
            for (int p = 0; p < 8; p++)
                #pragma unroll
                for (int j = 0; j < 8; j++)
                    fma2(acc[p][j], h[p], w[j]);
        }
    }

    // epilogue: store raw, fused sa/da + per-head global max
    int head = tx >> 1;
    int chb = (tx & 1) * 8;
    float lmax = -3.4e38f;
    #pragma unroll
    for (int p = 0; p < 8; p++) {
        float clo[8], chi[8];
        #pragma unroll
        for (int j = 0; j < 8; j++) unpack2(acc[p][j], clo[j], chi[j]);
        int row0 = r0 + ty * 16 + 2 * p;
        #pragma unroll
        for (int hh = 0; hh < 2; hh++) {
            const float* c = hh ? chi : clo;
            int row = row0 + hh;
            bool ok = row < n;
            if (ok) {
                *(float4*)&raw[(size_t)row * 256 + tx * 8]     = make_float4(c[0], c[1], c[2], c[3]);
                *(float4*)&raw[(size_t)row * 256 + tx * 8 + 4] = make_float4(c[4], c[5], c[6], c[7]);
            }
            float psa = 0.f, pda = 0.f;
            #pragma unroll
            for (int j = 0; j < 8; j++) {
                psa += c[j] * s_as[head * 16 + chb + j];
                pda += c[j] * s_ad[head * 16 + chb + j];
            }
            psa += __shfl_xor_sync(0xffffffffu, psa, 1);
            pda += __shfl_xor_sync(0xffffffffu, pda, 1);
            if (ok) {
                if ((tx & 1) == 0) {
                    g_sa[(size_t)row * 16 + head] = psa;
                    lmax = fmaxf(lmax, psa);
                } else {
                    g_da[(size_t)row * 16 + head] = pda;
                }
            }
        }
    }
    if ((tx & 1) == 0) atomicMax(&s_max[head], fenc(lmax));
    __syncthreads();
    if (tid < 16) atomicMax(&g_samaxi[layer * 16 + tid], s_max[tid]);
}

// -------- GAT aggregation: single pass using global sa-max bound --------
__global__ void k_gatagg(const float* __restrict__ bias, int n, int layer) {
    const float* __restrict__ raw = g_bufR;
    float* __restrict__ outF = g_bufF;
    int w = (blockIdx.x * blockDim.x + threadIdx.x) >> 5;
    if (w >= n) return;
    int lane = threadIdx.x & 31;
    int h16 = lane & 15;
    int beg = g_ptr[w], end = g_ptr[w + 1];
    float dval = g_da[(size_t)w * 16 + h16];
    float samax = fdec(g_samaxi[layer * 16 + h16]);
    float m = lrelu(samax + dval);   // >= true neighborhood max (lrelu monotone)

    float z = 0.f;
    float acc[8] = {0.f,0.f,0.f,0.f,0.f,0.f,0.f,0.f};
    {   // self loop
        float sa_self = g_sa[(size_t)w * 16 + h16];
        float eh = __expf(lrelu(sa_self + dval) - m);
        if (lane < 16) z += eh;
        float ew = __shfl_sync(0xffffffffu, eh, lane >> 1);
        const float4* hp = (const float4*)&raw[(size_t)w * 256 + lane * 8];
        float4 v0 = hp[0], v1 = hp[1];
        acc[0] += ew * v0.x; acc[1] += ew * v0.y; acc[2] += ew * v0.z; acc[3] += ew * v0.w;
        acc[4] += ew * v1.x; acc[5] += ew * v1.y; acc[6] += ew * v1.z; acc[7] += ew * v1.w;
    }
    #pragma unroll 2
    for (int e = beg; e < end; e++) {
        int s = g_csr[e];
        float eh = __expf(lrelu(g_sa[(size_t)s * 16 + h16] + dval) - m);
        if (lane < 16) z += eh;
        float ew = __shfl_sync(0xffffffffu, eh, lane >> 1);
        const float4* hp = (const float4*)&raw[(size_t)s * 256 + lane * 8];
        float4 v0 = hp[0], v1 = hp[1];
        acc[0] += ew * v0.x; acc[1] += ew * v0.y; acc[2] += ew * v0.z; acc[3] += ew * v0.w;
        acc[4] += ew * v1.x; acc[5] += ew * v1.y; acc[6] += ew * v1.z; acc[7] += ew * v1.w;
    }
    float zh = __shfl_sync(0xffffffffu, z, lane >> 1) + 1e-16f;
    float inv = 1.0f / zh;
    const float* bp = &bias[lane * 8];
    float4 o0, o1;
    o0.x = eluf(acc[0] * inv + bp[0]); o0.y = eluf(acc[1] * inv + bp[1]);
    o0.z = eluf(acc[2] * inv + bp[2]); o0.w = eluf(acc[3] * inv + bp[3]);
    o1.x = eluf(acc[4] * inv + bp[4]); o1.y = eluf(acc[5] * inv + bp[5]);
    o1.z = eluf(acc[6] * inv + bp[6]); o1.w = eluf(acc[7] * inv + bp[7]);
    *(float4*)&outF[(size_t)w * 256 + lane * 8]     = o0;
    *(float4*)&outF[(size_t)w * 256 + lane * 8 + 4] = o1;
}

// -------- final: concat(h[user], h[item]) @ Wdnn[512,2] -> log_softmax --------
__global__ void k_final(const float* __restrict__ Wdnn, const int* __restrict__ ui,
                        const int* __restrict__ ii, float* __restrict__ out, int Pn) {
    int p = (blockIdx.x * blockDim.x + threadIdx.x) >> 5;
    if (p >= Pn) return;
    int lane = threadIdx.x & 31;
    int u = ui[p], it = ii[p];
    float a0 = 0.f, a1 = 0.f;
    for (int i = lane; i < 512; i += 32) {
        float f = (i < 256) ? g_bufF[(size_t)u * 256 + i] : g_bufF[(size_t)it * 256 + (i - 256)];
        a0 += f * Wdnn[2 * i];
        a1 += f * Wdnn[2 * i + 1];
    }
    #pragma unroll
    for (int o = 16; o; o >>= 1) {
        a0 += __shfl_xor_sync(0xffffffffu, a0, o);
        a1 += __shfl_xor_sync(0xffffffffu, a1, o);
    }
    if (lane == 0) {
        float m = fmaxf(a0, a1);
        float l = logf(expf(a0 - m) + expf(a1 - m));
        out[2 * p]     = a0 - m - l;
        out[2 * p + 1] = a1 - m - l;
    }
}

extern "C" void kernel_launch(void* const* d_in, const int* in_sizes, int n_in,
                              void* d_out, int out_size) {
    const float* x    = (const float*)d_in[0];
    const int*   ei   = (const int*)d_in[1];
    const float* Hd   = (const float*)d_in[2];
    const int*   ui   = (const int*)d_in[3];
    const int*   ii   = (const int*)d_in[4];
    const float* Wgcn = (const float*)d_in[5];
    const float* bgcn = (const float*)d_in[6];
    const float* W1   = (const float*)d_in[7];
    const float* a1s  = (const float*)d_in[8];
    const float* a1d  = (const float*)d_in[9];
    const float* b1   = (const float*)d_in[10];
    const float* W2   = (const float*)d_in[11];
    const float* a2s  = (const float*)d_in[12];
    const float* a2d  = (const float*)d_in[13];
    const float* b2   = (const float*)d_in[14];
    const float* W3   = (const float*)d_in[15];
    const float* a3s  = (const float*)d_in[16];
    const float* a3d  = (const float*)d_in[17];
    const float* b3   = (const float*)d_in[18];
    const float* Wd   = (const float*)d_in[19];
    const float* Wr   = (const float*)d_in[20];
    const float* Wdnn = (const float*)d_in[21];
    float* out = (float*)d_out;

    int N = in_sizes[0] / 128;
    int E = in_sizes[1] / 2;
    int P = in_sizes[3];

    // CSR build + degrees
    k_zero<<<(N + 255) / 256, 256>>>(N);
    k_count<<<(E + 255) / 256, 256>>>(ei, E);
    k_scan<<<1, 1024>>>(N);
    k_scatter<<<(E + 255) / 256, 256>>>(ei, E);
    k_initmax<<<1, 64>>>();

    // dual conv collapse (reassociated): T1 = Hd@Wr ; Wcat = [Wgcn | Wd@T1]
    k_hdwr<<<32, 256>>>(Hd, Wr);
    k_wdT1<<<8, 256>>>(Wd, Wgcn);

    // xw = x @ Wcat
    k_xw<<<(N + 31) / 32, 256>>>(x, N);

    // GCN stage -> h0
    k_gcn<<<(N + 7) / 8, 256>>>(bgcn, N);

    int gB = (N + 127) / 128;
    int gA = (N + 7) / 8;

    k_gatgemm<<<gB, 256>>>(16,  W1, a1s, a1d, N, 0);
    k_gatagg<<<gA, 256>>>(b1, N, 0);
    k_gatgemm<<<gB, 256>>>(256, W2, a2s, a2d, N, 1);
    k_gatagg<<<gA, 256>>>(b2, N, 1);
    k_gatgemm<<<gB, 256>>>(256, W3, a3s, a3d, N, 2);
    k_gatagg<<<gA, 256>>>(b3, N, 2);

    k_final<<<(P + 7) / 8, 256>>>(Wdnn, ui, ii, out, P);
}